// round 1
// baseline (speedup 1.0000x reference)
#include <cuda_runtime.h>
#include <cstdint>

#define S_STEPS 19648   // B*N = 64*307
#define NCH 12          // T_IN: independent LSTM chains
#define HID 128
#define NROWS_TOTAL (S_STEPS * NCH)

// h history for deferred output projection: 19648*12*128 floats = ~115 MB
__device__ float g_hhist[(size_t)S_STEPS * NCH * HID];

__device__ __forceinline__ uint32_t smem_u32(const void* p) {
    uint32_t a;
    asm("{ .reg .u64 t; cvta.to.shared.u64 t, %1; cvt.u32.u64 %0, t; }"
        : "=r"(a) : "l"(p));
    return a;
}
__device__ __forceinline__ uint32_t my_cluster_rank() {
    uint32_t r; asm("mov.u32 %0, %%cluster_ctarank;" : "=r"(r)); return r;
}
__device__ __forceinline__ void remote_st_f32(uint32_t laddr, uint32_t peer, float v) {
    uint32_t raddr;
    asm volatile("mapa.shared::cluster.u32 %0, %1, %2;"
                 : "=r"(raddr) : "r"(laddr), "r"(peer));
    asm volatile("st.shared::cluster.f32 [%0], %1;" :: "r"(raddr), "f"(v) : "memory");
}
#define CLUSTER_SYNC() do { \
    asm volatile("barrier.cluster.arrive.aligned;" ::: "memory"); \
    asm volatile("barrier.cluster.wait.aligned;"   ::: "memory"); } while (0)

// 24 CTAs = 12 chains x 2-CTA clusters. Each CTA owns 64 hidden units
// (256 gate rows), weights fully register-resident (128 regs/thread).
__global__ void __launch_bounds__(256, 1) __cluster_dims__(2, 1, 1)
lstm_kernel(const float* __restrict__ x,
            const float* __restrict__ W_ih,
            const float* __restrict__ W_hh,
            const float* __restrict__ b_ih,
            const float* __restrict__ b_hh)
{
    __shared__ __align__(16) float h_sh[2][HID];  // double-buffered hidden state
    __shared__ float z_sh[256];                   // local gate pre-activations

    const int tid   = threadIdx.x;
    const uint32_t rank = my_cluster_rank();      // 0 or 1 within chain cluster
    const int chain = blockIdx.x >> 1;            // 0..11
    const int g_idx = tid >> 6;                   // gate 0..3 (i,f,g,o)
    const int u_l   = tid & 63;                   // local hidden unit 0..63
    const int row   = g_idx * 128 + (int)rank * 64 + u_l;  // row in W (4H x H)

    // Register-resident recurrent weights: 128 floats = 32 float4
    float4 w[32];
    const float4* wrow = reinterpret_cast<const float4*>(W_hh + (size_t)row * HID);
#pragma unroll
    for (int j = 0; j < 32; j++) w[j] = wrow[j];

    const float wx0 = W_ih[row * 3 + 0];
    const float wx1 = W_ih[row * 3 + 1];
    const float wx2 = W_ih[row * 3 + 2];
    const float bsum = b_ih[row] + b_hh[row];

    if (tid < HID) { h_sh[0][tid] = 0.f; h_sh[1][tid] = 0.f; }
    float c = 0.f;  // cell state, held by threads tid<64 (one per owned unit)
    CLUSTER_SYNC(); // init visible before peer's first remote store

    // x layout: (B,N,F,T) -> element (s, f, t) at x[s*36 + f*12 + t]
    float x0 = x[chain], x1 = x[12 + chain], x2 = x[24 + chain];

    for (int s = 0; s < S_STEPS; s++) {
        const int p = s & 1;

        // Prefetch next step's input (hidden under the matvec)
        float nx0 = 0.f, nx1 = 0.f, nx2 = 0.f;
        if (s + 1 < S_STEPS) {
            const float* xp = x + (size_t)(s + 1) * 36 + chain;
            nx0 = __ldg(xp); nx1 = __ldg(xp + 12); nx2 = __ldg(xp + 24);
        }

        // z_row = bsum + W_ih[row,:]*x + W_hh[row,:] . h
        const float4* h4 = reinterpret_cast<const float4*>(h_sh[p]);
        float a0 = 0.f, a1 = 0.f, a2 = 0.f, a3 = 0.f;
#pragma unroll
        for (int j = 0; j < 32; j++) {
            float4 hv = h4[j];   // broadcast LDS.128 (conflict-free)
            a0 = fmaf(w[j].x, hv.x, a0);
            a1 = fmaf(w[j].y, hv.y, a1);
            a2 = fmaf(w[j].z, hv.z, a2);
            a3 = fmaf(w[j].w, hv.w, a3);
        }
        float z = bsum + wx0 * x0 + wx1 * x1 + wx2 * x2 + ((a0 + a1) + (a2 + a3));
        z_sh[tid] = z;
        __syncthreads();

        if (tid < 64) {
            float zi = z_sh[tid],       zf = z_sh[64 + tid];
            float zg = z_sh[128 + tid], zo = z_sh[192 + tid];
            float si = 1.f / (1.f + __expf(-zi));
            float sf = 1.f / (1.f + __expf(-zf));
            float so = 1.f / (1.f + __expf(-zo));
            c = sf * c + si * tanhf(zg);
            float hv = so * tanhf(c);
            int u = (int)rank * 64 + tid;
            h_sh[p ^ 1][u] = hv;                                  // local copy
            remote_st_f32(smem_u32(&h_sh[p ^ 1][u]), rank ^ 1u, hv); // peer copy
            g_hhist[(size_t)(s * NCH + chain) * HID + u] = hv;     // for out proj
        }
        x0 = nx0; x1 = nx1; x2 = nx2;
        CLUSTER_SYNC();  // publishes h (local + remote DSMEM stores) for step s+1
    }
}

// Deferred output projection: out[row] = b_lin + h_hist[row,:] . W_lin
// One warp handles 8 rows; fully bandwidth-bound (~121 MB read).
__global__ void __launch_bounds__(256) out_kernel(
    const float* __restrict__ Wlin, const float* __restrict__ blin,
    float* __restrict__ out)
{
    const int lane = threadIdx.x & 31;
    const int warp = (blockIdx.x * blockDim.x + threadIdx.x) >> 5;
    const float w0 = Wlin[lane],      w1 = Wlin[lane + 32];
    const float w2 = Wlin[lane + 64], w3 = Wlin[lane + 96];
    const float bl = __ldg(blin);
    int row = warp * 8;
#pragma unroll
    for (int k = 0; k < 8; k++, row++) {
        if (row >= NROWS_TOTAL) return;
        const float* h = g_hhist + (size_t)row * HID;
        float s = h[lane] * w0 + h[lane + 32] * w1
                + h[lane + 64] * w2 + h[lane + 96] * w3;
#pragma unroll
        for (int off = 16; off; off >>= 1)
            s += __shfl_xor_sync(0xffffffffu, s, off);
        if (lane == 0) out[row] = s + bl;
    }
}

extern "C" void kernel_launch(void* const* d_in, const int* in_sizes, int n_in,
                              void* d_out, int out_size)
{
    const float* x     = (const float*)d_in[0];
    const float* W_ih  = (const float*)d_in[1];
    const float* W_hh  = (const float*)d_in[2];
    const float* b_ih  = (const float*)d_in[3];
    const float* b_hh  = (const float*)d_in[4];
    const float* W_lin = (const float*)d_in[5];
    const float* b_lin = (const float*)d_in[6];
    float* out = (float*)d_out;

    lstm_kernel<<<24, 256>>>(x, W_ih, W_hh, b_ih, b_hh);
    // 235776 rows / (8 rows/warp * 8 warps/block) = 3684 blocks
    out_kernel<<<3684, 256>>>(W_lin, b_lin, out);
}

// round 2
// speedup vs baseline: 1.7792x; 1.7792x over previous
#include <cuda_runtime.h>
#include <cstdint>

#define S_STEPS 19648   // B*N = 64*307 sequential LSTM steps
#define NCH 12          // T_IN: independent LSTM chains
#define HID 128
#define NROWS_TOTAL (S_STEPS * NCH)

// h history for deferred output projection: 19648*12*128 floats = ~115 MB
__device__ float g_hhist[(size_t)S_STEPS * NCH * HID];

// ---------------- PTX helpers ----------------
__device__ __forceinline__ uint32_t smem_u32(const void* p) {
    uint32_t a;
    asm("{ .reg .u64 t; cvta.to.shared.u64 t, %1; cvt.u32.u64 %0, t; }"
        : "=r"(a) : "l"(p));
    return a;
}
__device__ __forceinline__ uint32_t my_cluster_rank() {
    uint32_t r; asm("mov.u32 %0, %%cluster_ctarank;" : "=r"(r)); return r;
}
__device__ __forceinline__ uint32_t mapa_u32(uint32_t laddr, uint32_t peer) {
    uint32_t r;
    asm("mapa.shared::cluster.u32 %0, %1, %2;" : "=r"(r) : "r"(laddr), "r"(peer));
    return r;
}
// Remote shared store with mbarrier transaction tracking (peer's mbar).
__device__ __forceinline__ void st_async_f32(uint32_t raddr, float v, uint32_t rmbar) {
    asm volatile(
        "st.async.shared::cluster.mbarrier::complete_tx::bytes.b32 [%0], %1, [%2];"
        :: "r"(raddr), "r"(__float_as_uint(v)), "r"(rmbar) : "memory");
}
#define MBAR_INIT(a, n) \
    asm volatile("mbarrier.init.shared.b64 [%0], %1;" :: "r"(a), "r"((uint32_t)(n)) : "memory")
#define MBAR_EXPECT_TX(a, n) \
    asm volatile("mbarrier.arrive.expect_tx.shared.b64 _, [%0], %1;" :: "r"(a), "r"((uint32_t)(n)) : "memory")
#define MBAR_WAIT(a, par) do {                                              \
    asm volatile(                                                           \
        "{\n\t.reg .pred P1;\n\t"                                           \
        "WL_%=:\n\t"                                                        \
        "mbarrier.try_wait.parity.acquire.cta.shared::cta.b64 P1, [%0], %1, 0x989680;\n\t" \
        "@P1 bra.uni WD_%=;\n\t"                                            \
        "bra.uni WL_%=;\n\t"                                                \
        "WD_%=:\n\t}"                                                       \
        :: "r"(a), "r"((uint32_t)(par)) : "memory");                        \
} while (0)

// Packed f32x2 FMA: (d.lo,d.hi) = (a.lo*b.lo+c.lo, a.hi*b.hi+c.hi)
__device__ __forceinline__ unsigned long long fma2(unsigned long long a,
                                                   unsigned long long b,
                                                   unsigned long long c) {
    unsigned long long d;
    asm("fma.rn.f32x2 %0, %1, %2, %3;" : "=l"(d) : "l"(a), "l"(b), "l"(c));
    return d;
}
__device__ __forceinline__ float unpack_sum(unsigned long long a) {
    uint32_t lo, hi;
    asm("mov.b64 {%0, %1}, %2;" : "=r"(lo), "=r"(hi) : "l"(a));
    return __uint_as_float(lo) + __uint_as_float(hi);
}
__device__ __forceinline__ float tanh_fast(float x) {
    float y; asm("tanh.approx.f32 %0, %1;" : "=f"(y) : "f"(x)); return y;
}
__device__ __forceinline__ float sigmoid_fast(float x) {
    return fmaf(0.5f, tanh_fast(0.5f * x), 0.5f);
}
#define CLUSTER_SYNC() do { \
    asm volatile("barrier.cluster.arrive.aligned;" ::: "memory"); \
    asm volatile("barrier.cluster.wait.aligned;"   ::: "memory"); } while (0)

// ---------------- LSTM kernel ----------------
// 24 CTAs = 12 chains x 2-CTA clusters. Each CTA owns 64 hidden units
// (256 gate rows), recurrent weights fully register-resident (128 regs/thread
// as 64 packed f32x2). Warp w owns units 8w..8w+7; lane = gate*8 + unit_local,
// so gate redistribution is in-warp shuffles (no smem, no extra barrier).
__global__ void __launch_bounds__(256, 1) __cluster_dims__(2, 1, 1)
lstm_kernel(const float* __restrict__ x,
            const float* __restrict__ W_ih,
            const float* __restrict__ W_hh,
            const float* __restrict__ b_ih,
            const float* __restrict__ b_hh)
{
    __shared__ __align__(16) float h_sh[2][HID];   // double-buffered hidden state
    __shared__ __align__(8)  unsigned long long mbar[2];

    const int tid  = threadIdx.x;
    const int w    = tid >> 5;
    const int l    = tid & 31;
    const uint32_t rank = my_cluster_rank();
    const uint32_t peer = rank ^ 1u;
    const int chain = blockIdx.x >> 1;
    const int g     = l >> 3;               // gate 0..3
    const int ul    = 8 * w + (l & 7);      // local unit 0..63
    const int row   = g * 128 + (int)rank * 64 + ul;

    // Register-resident W_hh row, split into local-h half / remote-h half,
    // stored as packed f32x2 pairs. 16 ull2 each = 64 u64 regs = 128 regs.
    const ulonglong2* wrow = reinterpret_cast<const ulonglong2*>(W_hh + (size_t)row * HID);
    ulonglong2 wa[16], wb[16];
#pragma unroll
    for (int j = 0; j < 16; j++) wa[j] = wrow[(int)rank * 16 + j];
#pragma unroll
    for (int j = 0; j < 16; j++) wb[j] = wrow[(int)peer * 16 + j];

    const float wx0 = W_ih[row * 3 + 0];
    const float wx1 = W_ih[row * 3 + 1];
    const float wx2 = W_ih[row * 3 + 2];
    const float bsum = b_ih[row] + b_hh[row];

    if (tid < HID) h_sh[0][tid] = 0.f;

    const uint32_t mb_l0 = smem_u32(&mbar[0]);
    const uint32_t mb_l1 = smem_u32(&mbar[1]);
    if (tid == 0) {
        MBAR_INIT(mb_l0, 1);
        MBAR_INIT(mb_l1, 1);
        MBAR_EXPECT_TX(mb_l1, 256);   // fill during step 0 -> buffer 1
    }
    __syncthreads();
    CLUSTER_SYNC();  // mbar init + h zeros visible cluster-wide before any st.async

    // Precomputed remote targets (peer's h buffers + peer's mbarriers)
    const uint32_t r_h0  = mapa_u32(smem_u32(&h_sh[0][(int)rank * 64 + ul]), peer);
    const uint32_t r_h1  = mapa_u32(smem_u32(&h_sh[1][(int)rank * 64 + ul]), peer);
    const uint32_t r_mb0 = mapa_u32(mb_l0, peer);
    const uint32_t r_mb1 = mapa_u32(mb_l1, peer);

    float c = 0.f;        // cell state (lanes 0..7 of each warp)
    int ph0 = 0, ph1 = 0; // mbarrier phase parities

    // x layout: (B,N,F,T) -> element (s,f,t) at x[s*36 + f*12 + t]
    float x0 = x[chain], x1 = x[12 + chain], x2 = x[24 + chain];

#define LSTM_STEP(s, P)                                                        \
    {                                                                          \
        const int b = 1 - (P);                                                 \
        if (tid == 0 && (s) > 0 && (s) < S_STEPS - 1)                          \
            MBAR_EXPECT_TX((b) ? mb_l1 : mb_l0, 256);                          \
        /* prefetch next x */                                                  \
        float nx0 = 0.f, nx1 = 0.f, nx2 = 0.f;                                 \
        if ((s) + 1 < S_STEPS) {                                               \
            const float* xp = x + (size_t)((s) + 1) * 36 + chain;              \
            nx0 = __ldg(xp); nx1 = __ldg(xp + 12); nx2 = __ldg(xp + 24);       \
        }                                                                      \
        /* local-half matvec (our own 64 h, written locally last step) */      \
        const ulonglong2* hl =                                                 \
            reinterpret_cast<const ulonglong2*>(&h_sh[P][(int)rank * 64]);     \
        unsigned long long a0 = 0ull, a1 = 0ull;                               \
        _Pragma("unroll")                                                      \
        for (int j = 0; j < 16; j++) {                                         \
            ulonglong2 hv = hl[j];                                             \
            a0 = fma2(wa[j].x, hv.x, a0);                                      \
            a1 = fma2(wa[j].y, hv.y, a1);                                      \
        }                                                                      \
        /* wait for peer's 64 h (st.async tx into buffer P, mbar[P]) */        \
        if ((s) > 0) {                                                         \
            if (P) { MBAR_WAIT(mb_l1, ph1); ph1 ^= 1; }                        \
            else   { MBAR_WAIT(mb_l0, ph0); ph0 ^= 1; }                        \
        }                                                                      \
        const ulonglong2* hr =                                                 \
            reinterpret_cast<const ulonglong2*>(&h_sh[P][(int)peer * 64]);     \
        _Pragma("unroll")                                                      \
        for (int j = 0; j < 16; j++) {                                         \
            ulonglong2 hv = hr[j];                                             \
            a0 = fma2(wb[j].x, hv.x, a0);                                      \
            a1 = fma2(wb[j].y, hv.y, a1);                                      \
        }                                                                      \
        float z = bsum + wx0 * x0 + wx1 * x1 + wx2 * x2                        \
                + unpack_sum(a0) + unpack_sum(a1);                             \
        /* gather the 4 gates of my unit (all within this warp) */             \
        const unsigned fm = 0xffffffffu;                                       \
        float zi = __shfl_sync(fm, z, (l & 7));                                \
        float zf = __shfl_sync(fm, z, (l & 7) + 8);                            \
        float zg = __shfl_sync(fm, z, (l & 7) + 16);                           \
        float zo = __shfl_sync(fm, z, (l & 7) + 24);                           \
        if (l < 8) {                                                           \
            float si = sigmoid_fast(zi);                                       \
            float sf = sigmoid_fast(zf);                                       \
            float so = sigmoid_fast(zo);                                       \
            c = sf * c + si * tanh_fast(zg);                                   \
            float hv = so * tanh_fast(c);                                      \
            int u = (int)rank * 64 + ul;                                       \
            h_sh[b][u] = hv;                                                   \
            if ((s) + 1 < S_STEPS)                                             \
                st_async_f32((b) ? r_h1 : r_h0, hv, (b) ? r_mb1 : r_mb0);      \
            g_hhist[(size_t)((s) * NCH + chain) * HID + u] = hv;               \
        }                                                                      \
        __syncthreads();  /* local h writes visible; buffers rotate */         \
        x0 = nx0; x1 = nx1; x2 = nx2;                                          \
    }

    for (int s = 0; s < S_STEPS; s += 2) {
        LSTM_STEP(s, 0);
        LSTM_STEP(s + 1, 1);
    }
#undef LSTM_STEP
}

// Deferred output projection: out[row] = b_lin + h_hist[row,:] . W_lin
__global__ void __launch_bounds__(256) out_kernel(
    const float* __restrict__ Wlin, const float* __restrict__ blin,
    float* __restrict__ out)
{
    const int lane = threadIdx.x & 31;
    const int warp = (blockIdx.x * blockDim.x + threadIdx.x) >> 5;
    const float w0 = Wlin[lane],      w1 = Wlin[lane + 32];
    const float w2 = Wlin[lane + 64], w3 = Wlin[lane + 96];
    const float bl = __ldg(blin);
    int row = warp * 8;
#pragma unroll
    for (int k = 0; k < 8; k++, row++) {
        if (row >= NROWS_TOTAL) return;
        const float* h = g_hhist + (size_t)row * HID;
        float s = h[lane] * w0 + h[lane + 32] * w1
                + h[lane + 64] * w2 + h[lane + 96] * w3;
#pragma unroll
        for (int off = 16; off; off >>= 1)
            s += __shfl_xor_sync(0xffffffffu, s, off);
        if (lane == 0) out[row] = s + bl;
    }
}

extern "C" void kernel_launch(void* const* d_in, const int* in_sizes, int n_in,
                              void* d_out, int out_size)
{
    const float* x     = (const float*)d_in[0];
    const float* W_ih  = (const float*)d_in[1];
    const float* W_hh  = (const float*)d_in[2];
    const float* b_ih  = (const float*)d_in[3];
    const float* b_hh  = (const float*)d_in[4];
    const float* W_lin = (const float*)d_in[5];
    const float* b_lin = (const float*)d_in[6];
    float* out = (float*)d_out;

    lstm_kernel<<<24, 256>>>(x, W_ih, W_hh, b_ih, b_hh);
    out_kernel<<<3684, 256>>>(W_lin, b_lin, out);
}

// round 3
// speedup vs baseline: 2.3669x; 1.3303x over previous
#include <cuda_runtime.h>
#include <cstdint>

#define S_STEPS 19648   // B*N = 64*307 sequential LSTM steps
#define NCH 12          // T_IN: independent LSTM chains
#define HID 128
#define CLS 4           // CTAs per chain (cluster size)
#define NROWS_TOTAL (S_STEPS * NCH)

// h history for deferred output projection: 19648*12*128 floats = ~115 MB
__device__ float g_hhist[(size_t)S_STEPS * NCH * HID];

// ---------------- PTX helpers ----------------
__device__ __forceinline__ uint32_t smem_u32(const void* p) {
    uint32_t a;
    asm("{ .reg .u64 t; cvta.to.shared.u64 t, %1; cvt.u32.u64 %0, t; }"
        : "=r"(a) : "l"(p));
    return a;
}
__device__ __forceinline__ uint32_t my_cluster_rank() {
    uint32_t r; asm("mov.u32 %0, %%cluster_ctarank;" : "=r"(r)); return r;
}
__device__ __forceinline__ uint32_t mapa_u32(uint32_t laddr, uint32_t rk) {
    uint32_t r;
    asm("mapa.shared::cluster.u32 %0, %1, %2;" : "=r"(r) : "r"(laddr), "r"(rk));
    return r;
}
__device__ __forceinline__ void st_async_f32(uint32_t raddr, float v, uint32_t rmbar) {
    asm volatile(
        "st.async.shared::cluster.mbarrier::complete_tx::bytes.b32 [%0], %1, [%2];"
        :: "r"(raddr), "r"(__float_as_uint(v)), "r"(rmbar) : "memory");
}
#define MBAR_INIT(a, n) \
    asm volatile("mbarrier.init.shared.b64 [%0], %1;" :: "r"(a), "r"((uint32_t)(n)) : "memory")
#define MBAR_EXPECT_TX(a, n) \
    asm volatile("mbarrier.arrive.expect_tx.shared.b64 _, [%0], %1;" :: "r"(a), "r"((uint32_t)(n)) : "memory")
#define MBAR_WAIT(a, par) do {                                              \
    asm volatile(                                                           \
        "{\n\t.reg .pred P1;\n\t"                                           \
        "WL_%=:\n\t"                                                        \
        "mbarrier.try_wait.parity.acquire.cta.shared::cta.b64 P1, [%0], %1, 0x989680;\n\t" \
        "@P1 bra.uni WD_%=;\n\t"                                            \
        "bra.uni WL_%=;\n\t"                                                \
        "WD_%=:\n\t}"                                                       \
        :: "r"(a), "r"((uint32_t)(par)) : "memory");                        \
} while (0)

__device__ __forceinline__ unsigned long long fma2(unsigned long long a,
                                                   unsigned long long b,
                                                   unsigned long long c) {
    unsigned long long d;
    asm("fma.rn.f32x2 %0, %1, %2, %3;" : "=l"(d) : "l"(a), "l"(b), "l"(c));
    return d;
}
__device__ __forceinline__ float unpack_sum(unsigned long long a) {
    uint32_t lo, hi;
    asm("mov.b64 {%0, %1}, %2;" : "=r"(lo), "=r"(hi) : "l"(a));
    return __uint_as_float(lo) + __uint_as_float(hi);
}
__device__ __forceinline__ float tanh_fast(float x) {
    float y; asm("tanh.approx.f32 %0, %1;" : "=f"(y) : "f"(x)); return y;
}
__device__ __forceinline__ float sigmoid_fast(float x) {
    return fmaf(0.5f, tanh_fast(0.5f * x), 0.5f);
}
#define CLUSTER_SYNC() do { \
    asm volatile("barrier.cluster.arrive.aligned;" ::: "memory"); \
    asm volatile("barrier.cluster.wait.aligned;"   ::: "memory"); } while (0)

// ---------------- LSTM kernel ----------------
// 48 CTAs = 12 chains x 4-CTA clusters. CTA rank r owns hidden units
// [32r, 32r+32) = 128 gate rows. Thread (w,l): row = gate*128 + (32r+4w+(l&3)),
// gate = (l&15)>>2; lanes l and l^16 split the row's 128 columns in halves.
// ALL h propagation (including to self) is st.async + one mbarrier per step:
// no __syncthreads in the main loop.
__global__ void __launch_bounds__(256, 1) __cluster_dims__(CLS, 1, 1)
lstm_kernel(const float* __restrict__ x,
            const float* __restrict__ W_ih,
            const float* __restrict__ W_hh,
            const float* __restrict__ b_ih,
            const float* __restrict__ b_hh)
{
    __shared__ __align__(16) float h_sh[2][HID];   // double-buffered hidden state
    __shared__ __align__(8)  unsigned long long mbar[2];

    const int tid  = threadIdx.x;
    const int w    = tid >> 5;
    const int l    = tid & 31;
    const uint32_t rank = my_cluster_rank();
    const int chain = blockIdx.x / CLS;

    const int uin  = l & 3;                 // unit within warp's group of 4
    const int g    = (l & 15) >> 2;         // gate 0..3 (i,f,g,o)
    const int half = l >> 4;                // column half 0/1
    const int ug   = 32 * (int)rank + 4 * w + uin;   // global hidden unit of my row
    const int row  = g * 128 + ug;          // row in W (4H x H)

    // Register-resident W_hh half-row: 64 floats = 16 ull2 (32 regs)
    const ulonglong2* wrow =
        reinterpret_cast<const ulonglong2*>(W_hh + (size_t)row * HID) + half * 16;
    ulonglong2 wv[16];
#pragma unroll
    for (int j = 0; j < 16; j++) wv[j] = wrow[j];

    const float wx0 = W_ih[row * 3 + 0];
    const float wx1 = W_ih[row * 3 + 1];
    const float wx2 = W_ih[row * 3 + 2];
    const float bsum = b_ih[row] + b_hh[row];

    if (tid < HID) h_sh[0][tid] = 0.f;

    const uint32_t mb_l0 = smem_u32(&mbar[0]);
    const uint32_t mb_l1 = smem_u32(&mbar[1]);
    if (tid == 0) {
        MBAR_INIT(mb_l0, 1);
        MBAR_INIT(mb_l1, 1);
        MBAR_EXPECT_TX(mb_l1, 512);   // step 0 fills buffer 1 (4 ranks x 32 x 4B)
    }
    __syncthreads();   // local h_sh[0] zeros + mbar init done
    CLUSTER_SYNC();    // mbar init visible cluster-wide before any st.async

    // Precomputed st.async targets (h slot + mbar in every rank, both buffers)
    uint32_t rh[2][CLS], rmb[2][CLS];
    {
        const uint32_t la0 = smem_u32(&h_sh[0][ug]);
        const uint32_t la1 = smem_u32(&h_sh[1][ug]);
#pragma unroll
        for (int k = 0; k < CLS; k++) {
            rh[0][k]  = mapa_u32(la0, (uint32_t)k);
            rh[1][k]  = mapa_u32(la1, (uint32_t)k);
            rmb[0][k] = mapa_u32(mb_l0, (uint32_t)k);
            rmb[1][k] = mapa_u32(mb_l1, (uint32_t)k);
        }
    }

    float c = 0.f;        // cell state (lanes 0..3 of each warp)
    int ph0 = 0, ph1 = 0; // mbarrier phase parities

    // x layout: (B,N,F,T) -> element (s,f,t) at x[s*36 + f*12 + t]
    float x0 = x[chain], x1 = x[12 + chain], x2 = x[24 + chain];

#define LSTM_STEP(s, P)                                                        \
    {                                                                          \
        const int b = 1 - (P);                                                 \
        if (tid == 0 && (s) > 0 && (s) < S_STEPS - 1)                          \
            MBAR_EXPECT_TX((b) ? mb_l1 : mb_l0, 512);                          \
        /* prefetch next x (L2-resident, hidden under the wait) */             \
        float nx0 = 0.f, nx1 = 0.f, nx2 = 0.f;                                 \
        if ((s) + 1 < S_STEPS) {                                               \
            const float* xp = x + (size_t)((s) + 1) * 36 + chain;              \
            nx0 = __ldg(xp); nx1 = __ldg(xp + 12); nx2 = __ldg(xp + 24);       \
        }                                                                      \
        /* wait for all 128 h of step s (st.async from all 4 ranks) */         \
        if ((s) > 0) {                                                         \
            if (P) { MBAR_WAIT(mb_l1, ph1); ph1 ^= 1; }                        \
            else   { MBAR_WAIT(mb_l0, ph0); ph0 ^= 1; }                        \
        }                                                                      \
        /* half-row matvec: 32 fma2, 4 independent accumulator chains */       \
        const ulonglong2* h4 =                                                 \
            reinterpret_cast<const ulonglong2*>(&h_sh[P][half * 64]);          \
        unsigned long long a0 = 0ull, a1 = 0ull, a2 = 0ull, a3 = 0ull;         \
        _Pragma("unroll")                                                      \
        for (int j = 0; j < 16; j += 2) {                                      \
            ulonglong2 hva = h4[j];                                            \
            a0 = fma2(wv[j].x, hva.x, a0);                                     \
            a1 = fma2(wv[j].y, hva.y, a1);                                     \
            ulonglong2 hvb = h4[j + 1];                                        \
            a2 = fma2(wv[j + 1].x, hvb.x, a2);                                 \
            a3 = fma2(wv[j + 1].y, hvb.y, a3);                                 \
        }                                                                      \
        float zs = (unpack_sum(a0) + unpack_sum(a1))                           \
                 + (unpack_sum(a2) + unpack_sum(a3));                          \
        const unsigned fm = 0xffffffffu;                                       \
        zs += __shfl_xor_sync(fm, zs, 16);                                     \
        float z = zs + bsum + wx0 * x0 + wx1 * x1 + wx2 * x2;                  \
        /* gather 4 gates of unit (lanes 4g+u, all in this warp) */            \
        float zi = __shfl_sync(fm, z, uin);                                    \
        float zf = __shfl_sync(fm, z, uin + 4);                                \
        float zg = __shfl_sync(fm, z, uin + 8);                                \
        float zo = __shfl_sync(fm, z, uin + 12);                               \
        if (l < 4) {                                                           \
            float si = sigmoid_fast(zi);                                       \
            float sf = sigmoid_fast(zf);                                       \
            float so = sigmoid_fast(zo);                                       \
            c = sf * c + si * tanh_fast(zg);                                   \
            float hv = so * tanh_fast(c);                                      \
            if ((s) + 1 < S_STEPS) {                                           \
                _Pragma("unroll")                                              \
                for (int k = 0; k < CLS; k++)                                  \
                    st_async_f32(rh[b][k], hv, rmb[b][k]);                     \
            }                                                                  \
            g_hhist[(size_t)((s) * NCH + chain) * HID + ug] = hv;              \
        }                                                                      \
        x0 = nx0; x1 = nx1; x2 = nx2;                                          \
    }

    for (int s = 0; s < S_STEPS; s += 2) {
        LSTM_STEP(s, 0);
        LSTM_STEP(s + 1, 1);
    }
#undef LSTM_STEP
}

// Deferred output projection: out[row] = b_lin + h_hist[row,:] . W_lin
__global__ void __launch_bounds__(256) out_kernel(
    const float* __restrict__ Wlin, const float* __restrict__ blin,
    float* __restrict__ out)
{
    const int lane = threadIdx.x & 31;
    const int warp = (blockIdx.x * blockDim.x + threadIdx.x) >> 5;
    const float w0 = Wlin[lane],      w1 = Wlin[lane + 32];
    const float w2 = Wlin[lane + 64], w3 = Wlin[lane + 96];
    const float bl = __ldg(blin);
    int row = warp * 8;
#pragma unroll
    for (int k = 0; k < 8; k++, row++) {
        if (row >= NROWS_TOTAL) return;
        const float* h = g_hhist + (size_t)row * HID;
        float s = h[lane] * w0 + h[lane + 32] * w1
                + h[lane + 64] * w2 + h[lane + 96] * w3;
#pragma unroll
        for (int off = 16; off; off >>= 1)
            s += __shfl_xor_sync(0xffffffffu, s, off);
        if (lane == 0) out[row] = s + bl;
    }
}

extern "C" void kernel_launch(void* const* d_in, const int* in_sizes, int n_in,
                              void* d_out, int out_size)
{
    const float* x     = (const float*)d_in[0];
    const float* W_ih  = (const float*)d_in[1];
    const float* W_hh  = (const float*)d_in[2];
    const float* b_ih  = (const float*)d_in[3];
    const float* b_hh  = (const float*)d_in[4];
    const float* W_lin = (const float*)d_in[5];
    const float* b_lin = (const float*)d_in[6];
    float* out = (float*)d_out;

    lstm_kernel<<<12 * CLS, 256>>>(x, W_ih, W_hh, b_ih, b_hh);
    out_kernel<<<3684, 256>>>(W_lin, b_lin, out);
}